// round 15
// baseline (speedup 1.0000x reference)
#include <cuda_runtime.h>
#include <cuda_bf16.h>
#include <cstdint>

#define NTOK   294
#define NTOKP  304
#define HEADS  8
#define DH     32
#define DIM    256
#define NWIN   256
#define NBIAS  1859
#define QSCALE 0.17677669529663687f  // 32^-0.5
#define LOG2E  1.4426950408889634f
#define XSZ    (6 * 16 * 16 * 7 * 7 * 256)   // 19267584

// ---------------- scratch (allocation-free: __device__ globals) -------------
__device__ __nv_bfloat16 g_x_hi[XSZ];
__device__ __nv_bfloat16 g_x_lo[XSZ];
__device__ __nv_bfloat16 g_wq_hi[768 * 256];
__device__ __nv_bfloat16 g_wq_lo[768 * 256];
__device__ __nv_bfloat16 g_wo_hi[256 * 256];
__device__ __nv_bfloat16 g_wo_lo[256 * 256];
// q/k/v as bf16 hi/lo, layout [wh][NTOK][32]
__device__ __nv_bfloat16 g_qh[NWIN * HEADS * NTOK * DH];
__device__ __nv_bfloat16 g_ql[NWIN * HEADS * NTOK * DH];
__device__ __nv_bfloat16 g_kh[NWIN * HEADS * NTOK * DH];
__device__ __nv_bfloat16 g_kl[NWIN * HEADS * NTOK * DH];
__device__ __nv_bfloat16 g_vh[NWIN * HEADS * NTOK * DH];
__device__ __nv_bfloat16 g_vl[NWIN * HEADS * NTOK * DH];
// attention output as bf16 hi/lo, layout [w][tok][256]
__device__ __nv_bfloat16 g_oh[NWIN * NTOK * DIM];
__device__ __nv_bfloat16 g_ol[NWIN * NTOK * DIM];

// ---------------- helpers ---------------------------------------------------
__device__ __forceinline__ uint32_t smem_u32(const void* p) {
    uint32_t a;
    asm("{ .reg .u64 t; cvta.to.shared.u64 t, %1; cvt.u32.u64 %0, t; }" : "=r"(a) : "l"(p));
    return a;
}

#define LDSM4(r, a) \
    asm volatile("ldmatrix.sync.aligned.m8n8.x4.shared.b16 {%0,%1,%2,%3}, [%4];" \
        : "=r"((r)[0]), "=r"((r)[1]), "=r"((r)[2]), "=r"((r)[3]) : "r"(a))
#define LDSM4T(r, a) \
    asm volatile("ldmatrix.sync.aligned.m8n8.x4.trans.shared.b16 {%0,%1,%2,%3}, [%4];" \
        : "=r"((r)[0]), "=r"((r)[1]), "=r"((r)[2]), "=r"((r)[3]) : "r"(a))

#define MMA16816(d, a, b0, b1) \
    asm volatile("mma.sync.aligned.m16n8k16.row.col.f32.bf16.bf16.f32 " \
        "{%0,%1,%2,%3}, {%4,%5,%6,%7}, {%8,%9}, {%0,%1,%2,%3};" \
        : "+f"((d)[0]), "+f"((d)[1]), "+f"((d)[2]), "+f"((d)[3]) \
        : "r"((a)[0]), "r"((a)[1]), "r"((a)[2]), "r"((a)[3]), "r"(b0), "r"(b1))

#define CP16(dst, src, sz) \
    asm volatile("cp.async.cg.shared.global [%0], [%1], 16, %2;" \
        :: "r"(dst), "l"(src), "r"(sz))
#define CP_COMMIT() asm volatile("cp.async.commit_group;" ::: "memory")
#define CP_WAIT1()  asm volatile("cp.async.wait_group 1;" ::: "memory")
#define CP_WAIT0()  asm volatile("cp.async.wait_group 0;" ::: "memory")

#define EX2F(d, x) asm("ex2.approx.f32 %0, %1;" : "=f"(d) : "f"(x))

// pack two floats into bf16x2 (one cvt instruction)
__device__ __forceinline__ uint32_t pack2(float lo, float hi) {
    uint32_t r;
    asm("cvt.rn.bf16x2.f32 %0, %1, %2;" : "=r"(r) : "f"(hi), "f"(lo));
    return r;
}
// hi/lo split pair
__device__ __forceinline__ void pack_hl(float a, float b, uint32_t& hi, uint32_t& lo) {
    hi = pack2(a, b);
    float fa = __uint_as_float(hi << 16);
    float fb = __uint_as_float(hi & 0xffff0000u);
    lo = pack2(a - fa, b - fb);
}
__device__ __forceinline__ void split_pack(float4 v, uint2& hi, uint2& lo) {
    pack_hl(v.x, v.y, hi.x, lo.x);
    pack_hl(v.z, v.w, hi.y, lo.y);
}

// GEMM smem: 2 stages x (AHI|ALO|BHI|BLO); tile = 128 rows x 32 cols bf16,
// 80B padded row stride -> conflict-free, no swizzle.
#define TILE_BYTES 10240
#define STAGE_BYTES 40960
#define T_AHI 0
#define T_ALO 10240
#define T_BHI 20480
#define T_BLO 30720
#define SM_RB (2 * STAGE_BYTES)
#define SM_GEMM_TOTAL (2 * STAGE_BYTES + 512)

// attention smem layout (bytes); rows padded to 40 bf16 = 80B
#define A_KH 0
#define A_KL 24320
#define A_VH 48640
#define A_VL 72960
#define A_BH 97280                      // 1859 floats (pre-scaled by log2e)
#define A_CJ 104716                     // 304 ints
#define ATTN_SMEM 105936

// ---------------- prep kernels ----------------------------------------------
__global__ __launch_bounds__(256) void split_x_kernel(const float* __restrict__ x)
{
    int i = blockIdx.x * blockDim.x + threadIdx.x;
    if (i < XSZ / 4) {
        float4 v = ((const float4*)x)[i];
        uint2 hi, lo;
        split_pack(v, hi, lo);
        ((uint2*)g_x_hi)[i] = hi;
        ((uint2*)g_x_lo)[i] = lo;
    }
}

__global__ __launch_bounds__(256) void split_w_kernel(const float* __restrict__ wqkv,
                                                      const float* __restrict__ wout)
{
    int i = blockIdx.x * blockDim.x + threadIdx.x;
    const int NQ4 = 768 * 256 / 4;
    const int NO4 = 256 * 256 / 4;
    if (i < NQ4) {
        float4 v = ((const float4*)wqkv)[i];
        uint2 hi, lo;
        split_pack(v, hi, lo);
        ((uint2*)g_wq_hi)[i] = hi;
        ((uint2*)g_wq_lo)[i] = lo;
    } else if (i < NQ4 + NO4) {
        int j = i - NQ4;
        float4 v = ((const float4*)wout)[j];
        uint2 hi, lo;
        split_pack(v, hi, lo);
        ((uint2*)g_wo_hi)[j] = hi;
        ((uint2*)g_wo_lo)[j] = lo;
    }
}

// ---------------- stage loaders (cp.async, 16B granules, 32-col chunks) -----
__device__ __forceinline__ void qkv_stage(uint32_t smb, int stg, int chunk,
                                          const int* rb, int bx, int tid)
{
    #pragma unroll
    for (int i = 0; i < 8; i++) {
        int u = tid + i * 256;
        int tile = u >> 9;
        int uu = u & 511;
        int row = uu >> 2, kc = uu & 3;
        uint32_t dst = smb + (uint32_t)stg * STAGE_BYTES + tile * TILE_BYTES
                       + row * 80 + kc * 16;
        const __nv_bfloat16* src;
        uint32_t sz = 16;
        if (tile < 2) {
            int base = rb[row];
            if (base < 0) { sz = 0; base = 0; }
            src = (tile == 0 ? g_x_hi : g_x_lo) + base + chunk * 32 + kc * 8;
        } else {
            int nrow = bx * 128 + row;
            src = (tile == 2 ? g_wq_hi : g_wq_lo) + nrow * 256 + chunk * 32 + kc * 8;
        }
        CP16(dst, src, sz);
    }
}

__device__ __forceinline__ void out_stage(uint32_t smb, int stg, int chunk,
                                          int bx, int by, int w, int tid)
{
    #pragma unroll
    for (int i = 0; i < 8; i++) {
        int u = tid + i * 256;
        int tile = u >> 9;
        int uu = u & 511;
        int row = uu >> 2, kc = uu & 3;
        uint32_t dst = smb + (uint32_t)stg * STAGE_BYTES + tile * TILE_BYTES
                       + row * 80 + kc * 16;
        const __nv_bfloat16* src;
        uint32_t sz = 16;
        if (tile < 2) {
            int tok = by * 128 + row;
            size_t base = 0;
            if (tok < NTOK) base = ((size_t)w * NTOK + tok) * DIM;
            else sz = 0;
            src = (tile == 0 ? g_oh : g_ol) + base + chunk * 32 + kc * 8;
        } else {
            int nrow = bx * 128 + row;
            src = (tile == 2 ? g_wo_hi : g_wo_lo) + nrow * 256 + chunk * 32 + kc * 8;
        }
        CP16(dst, src, sz);
    }
}

// ---------------------------------------------------------------------------
// Kernel 1: QKV GEMM. grid (6, 3, 256), block 256.
// Warps whose 32-row slice is entirely padding (by==2, wm>=2 -> rows >= 320)
// skip LDSM+MMA entirely (epilogue never stores those rows; staging zero-fills).
// ---------------------------------------------------------------------------
__global__ __launch_bounds__(256, 2) void qkv_kernel()
{
    extern __shared__ char sm[];
    const uint32_t smb = smem_u32(sm);
    int* rb = (int*)(sm + SM_RB);

    const int bx = blockIdx.x;
    const int by = blockIdx.y;
    const int w  = blockIdx.z;
    const int tid = threadIdx.x;
    const int lane = tid & 31, wid = tid >> 5;
    const int wm = wid & 3, wn = wid >> 2;
    const int hx = w >> 4, wy = w & 15;
    const bool do_mma = !(by == 2 && wm >= 2);   // rows >= 320 are all padding

    if (tid < 128) {
        int n = by * 128 + tid;
        if (n < NTOK) {
            int l = n / 49; int rem = n - l * 49; int w1 = rem / 7; int w2 = rem - w1 * 7;
            rb[tid] = ((l * 256 + hx * 16 + wy) * 49 + w1 * 7 + w2) * 256;
        } else rb[tid] = -1;
    }
    __syncthreads();

    float acc[2][8][4];
    #pragma unroll
    for (int mt = 0; mt < 2; mt++)
        #pragma unroll
        for (int nt = 0; nt < 8; nt++)
            #pragma unroll
            for (int r = 0; r < 4; r++) acc[mt][nt][r] = 0.f;

    const int l7 = lane & 7;
    const int g = lane >> 3;
    const uint32_t arow0 = (uint32_t)(wm * 32 + (lane & 15)) * 80;
    const int acg = lane >> 4;
    const uint32_t brow0 = (uint32_t)(wn * 64 + ((g & 2) << 2) + l7) * 80;
    const int bcg = g & 1;

    qkv_stage(smb, 0, 0, rb, bx, tid);
    CP_COMMIT();

    for (int chunk = 0; chunk < 8; chunk++) {
        if (chunk < 7) {
            qkv_stage(smb, (chunk + 1) & 1, chunk + 1, rb, bx, tid);
            CP_COMMIT();
            CP_WAIT1();
        } else {
            CP_WAIT0();
        }
        __syncthreads();

        if (do_mma) {
            const uint32_t sb = smb + (uint32_t)(chunk & 1) * STAGE_BYTES;
            #pragma unroll
            for (int ks = 0; ks < 2; ks++) {
                uint32_t ah[2][4], al[2][4], bh[4][4], bl[4][4];
                uint32_t akc = (uint32_t)(ks * 2 + acg) << 4;
                LDSM4(ah[0], sb + T_AHI + arow0 + akc);
                LDSM4(ah[1], sb + T_AHI + arow0 + 1280 + akc);
                LDSM4(al[0], sb + T_ALO + arow0 + akc);
                LDSM4(al[1], sb + T_ALO + arow0 + 1280 + akc);
                uint32_t bkc = (uint32_t)(ks * 2 + bcg) << 4;
                #pragma unroll
                for (int p = 0; p < 4; p++) {
                    LDSM4(bh[p], sb + T_BHI + brow0 + p * 1280 + bkc);
                    LDSM4(bl[p], sb + T_BLO + brow0 + p * 1280 + bkc);
                }
                #pragma unroll
                for (int mt = 0; mt < 2; mt++)
                    #pragma unroll
                    for (int nt = 0; nt < 8; nt++) {
                        uint32_t h0 = bh[nt >> 1][(nt & 1) * 2], h1 = bh[nt >> 1][(nt & 1) * 2 + 1];
                        uint32_t lo0 = bl[nt >> 1][(nt & 1) * 2], lo1 = bl[nt >> 1][(nt & 1) * 2 + 1];
                        MMA16816(acc[mt][nt], ah[mt], h0, h1);
                        MMA16816(acc[mt][nt], al[mt], h0, h1);
                        MMA16816(acc[mt][nt], ah[mt], lo0, lo1);
                    }
            }
        }
        __syncthreads();
    }

    // ---- epilogue: split + scatter to bf16 hi/lo q/k/v ---------------------
    const int part = bx >> 1;
    __nv_bfloat16* dh_ = (part == 0) ? g_qh : (part == 1) ? g_kh : g_vh;
    __nv_bfloat16* dl_ = (part == 0) ? g_ql : (part == 1) ? g_kl : g_vl;
    const float scale = (part == 0) ? QSCALE : 1.f;
    const int trow = lane >> 2;
    const int tcol2 = (lane & 3) * 2;

    #pragma unroll
    for (int mt = 0; mt < 2; mt++) {
        #pragma unroll
        for (int half = 0; half < 2; half++) {
            int r = by * 128 + wm * 32 + mt * 16 + trow + half * 8;
            if (r >= NTOK) continue;
            #pragma unroll
            for (int nt = 0; nt < 8; nt++) {
                int o = bx * 128 + wn * 64 + nt * 8 + tcol2;
                int hh = (o & 255) >> 5, d = o & 31;
                uint32_t hip, lop;
                pack_hl(acc[mt][nt][half * 2] * scale,
                        acc[mt][nt][half * 2 + 1] * scale, hip, lop);
                size_t off = ((size_t)(w * 8 + hh) * NTOK + r) * 32 + d;
                *(uint32_t*)(dh_ + off) = hip;
                *(uint32_t*)(dl_ + off) = lop;
            }
        }
    }
}

// ---------------------------------------------------------------------------
// Kernel 2: tensor-core attention. Warp 9's mt=1 tile (rows 304-319) is all
// padding -> skip its S/exp/PV work.
// ---------------------------------------------------------------------------
__global__ __launch_bounds__(320, 2) void attn_kernel(const float* __restrict__ bias_table)
{
    extern __shared__ char sm[];
    const uint32_t smb = smem_u32(sm);
    float* bH  = (float*)(sm + A_BH);
    int*   cjs = (int*)(sm + A_CJ);

    const int wh = blockIdx.x;
    const int h  = wh & 7;
    const int w  = wh >> 3;
    const int tid = threadIdx.x;
    const int lane = tid & 31, wm = tid >> 5;
    const int t4 = lane & 3, g = lane >> 2;
    const size_t base = (size_t)wh * NTOK * DH;

    {
        const __nv_bfloat16* srcs[4] = {g_kh + base, g_kl + base, g_vh + base, g_vl + base};
        const uint32_t dsts[4] = {A_KH, A_KL, A_VH, A_VL};
        for (int idx = tid; idx < 4 * NTOKP * 4; idx += 320) {
            int arr = idx / (NTOKP * 4);
            int rem = idx - arr * (NTOKP * 4);
            int row = rem >> 2, seg = rem & 3;
            uint32_t sz = (row < NTOK) ? 16u : 0u;
            int srow = (row < NTOK) ? row : 0;
            CP16(smb + dsts[arr] + row * 80 + seg * 16, srcs[arr] + srow * 32 + seg * 8, sz);
        }
        CP_COMMIT();
        for (int i = tid; i < NBIAS; i += 320) bH[i] = bias_table[i * HEADS + h] * LOG2E;
        for (int i = tid; i < NTOKP; i += 320) {
            if (i < NTOK) {
                int l = i / 49, rem = i - l * 49, w1 = rem / 7, w2 = rem - w1 * 7;
                cjs[i] = l * 169 + w1 * 13 + w2;
            } else cjs[i] = 0;
        }
    }

    const int R = wm * 32;
    const bool m1 = (R + 16 < NTOK);          // false only for warp 9 (rows 304+)
    uint32_t aQh[2][2][4], aQl[2][2][4];
    #pragma unroll
    for (int mt = 0; mt < 2; mt++) {
        int r0 = R + mt * 16 + g, r1 = r0 + 8;
        #pragma unroll
        for (int kh = 0; kh < 2; kh++) {
            int c0 = kh * 16 + 2 * t4, c1 = c0 + 8;
            aQh[mt][kh][0] = (r0 < NTOK) ? *(const uint32_t*)(g_qh + base + r0 * 32 + c0) : 0u;
            aQh[mt][kh][1] = (r1 < NTOK) ? *(const uint32_t*)(g_qh + base + r1 * 32 + c0) : 0u;
            aQh[mt][kh][2] = (r0 < NTOK) ? *(const uint32_t*)(g_qh + base + r0 * 32 + c1) : 0u;
            aQh[mt][kh][3] = (r1 < NTOK) ? *(const uint32_t*)(g_qh + base + r1 * 32 + c1) : 0u;
            aQl[mt][kh][0] = (r0 < NTOK) ? *(const uint32_t*)(g_ql + base + r0 * 32 + c0) : 0u;
            aQl[mt][kh][1] = (r1 < NTOK) ? *(const uint32_t*)(g_ql + base + r1 * 32 + c0) : 0u;
            aQl[mt][kh][2] = (r0 < NTOK) ? *(const uint32_t*)(g_ql + base + r0 * 32 + c1) : 0u;
            aQl[mt][kh][3] = (r1 < NTOK) ? *(const uint32_t*)(g_ql + base + r1 * 32 + c1) : 0u;
        }
    }
    CP_WAIT0();
    __syncthreads();

    int ci[2][2];
    #pragma unroll
    for (int mt = 0; mt < 2; mt++) {
        int r0 = R + mt * 16 + g, r1 = r0 + 8;
        ci[mt][0] = cjs[r0 < NTOK ? r0 : NTOK - 1] + 929;
        ci[mt][1] = cjs[r1 < NTOK ? r1 : NTOK - 1] + 929;
    }

    float O[2][4][4];
    #pragma unroll
    for (int mt = 0; mt < 2; mt++)
        #pragma unroll
        for (int dn = 0; dn < 4; dn++)
            #pragma unroll
            for (int e = 0; e < 4; e++) O[mt][dn][e] = 0.f;
    float rs[2][2] = {{0.f, 0.f}, {0.f, 0.f}};

    const int lrow = ((lane & 8) ? 8 : 0) + (lane & 7);
    const int lcol = (lane & 16) ? 8 : 0;

    for (int j0 = 0; j0 < NTOKP; j0 += 16) {
        int   cjv[2][2];
        bool  va[2][2];
        #pragma unroll
        for (int jn = 0; jn < 2; jn++) {
            int jb = j0 + 8 * jn + 2 * t4;
            cjv[jn][0] = cjs[jb];
            cjv[jn][1] = cjs[jb + 1];
            va[jn][0] = (jb < NTOK);
            va[jn][1] = (jb + 1 < NTOK);
        }
        float bb[2][2][4];
        #pragma unroll
        for (int mt = 0; mt < 2; mt++) {
            if (mt == 1 && !m1) continue;
            #pragma unroll
            for (int jn = 0; jn < 2; jn++) {
                bb[mt][jn][0] = bH[ci[mt][0] - cjv[jn][0]];
                bb[mt][jn][1] = bH[ci[mt][0] - cjv[jn][1]];
                bb[mt][jn][2] = bH[ci[mt][1] - cjv[jn][0]];
                bb[mt][jn][3] = bH[ci[mt][1] - cjv[jn][1]];
            }
        }

        uint32_t bkh[2][2][2], bkl[2][2][2];
        #pragma unroll
        for (int kh = 0; kh < 2; kh++) {
            uint32_t addr = (uint32_t)((j0 + lrow) * 80 + (kh * 16 + lcol) * 2);
            uint32_t t[4];
            LDSM4(t, smb + A_KH + addr);
            bkh[0][kh][0] = t[0]; bkh[0][kh][1] = t[2];
            bkh[1][kh][0] = t[1]; bkh[1][kh][1] = t[3];
            LDSM4(t, smb + A_KL + addr);
            bkl[0][kh][0] = t[0]; bkl[0][kh][1] = t[2];
            bkl[1][kh][0] = t[1]; bkl[1][kh][1] = t[3];
        }
        uint32_t bvh[4][2], bvl[4][2];
        #pragma unroll
        for (int dh2 = 0; dh2 < 2; dh2++) {
            uint32_t addr = (uint32_t)((j0 + lrow) * 80 + (dh2 * 16 + lcol) * 2);
            uint32_t t[4];
            LDSM4T(t, smb + A_VH + addr);
            bvh[dh2 * 2][0] = t[0]; bvh[dh2 * 2][1] = t[1];
            bvh[dh2 * 2 + 1][0] = t[2]; bvh[dh2 * 2 + 1][1] = t[3];
            LDSM4T(t, smb + A_VL + addr);
            bvl[dh2 * 2][0] = t[0]; bvl[dh2 * 2][1] = t[1];
            bvl[dh2 * 2 + 1][0] = t[2]; bvl[dh2 * 2 + 1][1] = t[3];
        }

        float S[2][2][4];
        #pragma unroll
        for (int mt = 0; mt < 2; mt++) {
            if (mt == 1 && !m1) continue;
            #pragma unroll
            for (int jn = 0; jn < 2; jn++) {
                #pragma unroll
                for (int e = 0; e < 4; e++) S[mt][jn][e] = 0.f;
                #pragma unroll
                for (int kh = 0; kh < 2; kh++) {
                    MMA16816(S[mt][jn], aQh[mt][kh], bkh[jn][kh][0], bkh[jn][kh][1]);
                    MMA16816(S[mt][jn], aQl[mt][kh], bkh[jn][kh][0], bkh[jn][kh][1]);
                    MMA16816(S[mt][jn], aQh[mt][kh], bkl[jn][kh][0], bkl[jn][kh][1]);
                }
            }
        }

        uint32_t aPh[2][4], aPl[2][4];
        #pragma unroll
        for (int mt = 0; mt < 2; mt++) {
            if (mt == 1 && !m1) continue;
            float p[2][4];
            #pragma unroll
            for (int jn = 0; jn < 2; jn++) {
                #pragma unroll
                for (int e = 0; e < 4; e++) {
                    float arg = fmaf(S[mt][jn][e], LOG2E, bb[mt][jn][e]);
                    float ex; EX2F(ex, arg);
                    p[jn][e] = va[jn][e & 1] ? ex : 0.f;
                }
                rs[mt][0] += p[jn][0] + p[jn][1];
                rs[mt][1] += p[jn][2] + p[jn][3];
            }
            pack_hl(p[0][0], p[0][1], aPh[mt][0], aPl[mt][0]);
            pack_hl(p[0][2], p[0][3], aPh[mt][1], aPl[mt][1]);
            pack_hl(p[1][0], p[1][1], aPh[mt][2], aPl[mt][2]);
            pack_hl(p[1][2], p[1][3], aPh[mt][3], aPl[mt][3]);
        }

        #pragma unroll
        for (int mt = 0; mt < 2; mt++) {
            if (mt == 1 && !m1) continue;
            #pragma unroll
            for (int dn = 0; dn < 4; dn++) {
                MMA16816(O[mt][dn], aPh[mt], bvh[dn][0], bvh[dn][1]);
                MMA16816(O[mt][dn], aPl[mt], bvh[dn][0], bvh[dn][1]);
                MMA16816(O[mt][dn], aPh[mt], bvl[dn][0], bvl[dn][1]);
            }
        }
    }

    #pragma unroll
    for (int mt = 0; mt < 2; mt++)
        #pragma unroll
        for (int h2 = 0; h2 < 2; h2++) {
            float v = rs[mt][h2];
            v += __shfl_xor_sync(0xFFFFFFFFu, v, 1);
            v += __shfl_xor_sync(0xFFFFFFFFu, v, 2);
            rs[mt][h2] = 1.f / v;
        }
    #pragma unroll
    for (int mt = 0; mt < 2; mt++)
        #pragma unroll
        for (int h2 = 0; h2 < 2; h2++) {
            int row = R + mt * 16 + g + 8 * h2;
            if (row >= NTOK) continue;
            float inv = rs[mt][h2];
            size_t ob = ((size_t)w * NTOK + row) * DIM + h * DH;
            #pragma unroll
            for (int dn = 0; dn < 4; dn++) {
                int col = dn * 8 + 2 * t4;
                uint32_t hip, lop;
                pack_hl(O[mt][dn][h2 * 2] * inv, O[mt][dn][h2 * 2 + 1] * inv, hip, lop);
                *(uint32_t*)(g_oh + ob + col) = hip;
                *(uint32_t*)(g_ol + ob + col) = lop;
            }
        }
}

// ---------------------------------------------------------------------------
// Kernel 3: output GEMM. grid (2, 3, 256), block 256. Same padding-warp skip.
// ---------------------------------------------------------------------------
__global__ __launch_bounds__(256, 2) void out_kernel(float* __restrict__ out)
{
    extern __shared__ char sm[];
    const uint32_t smb = smem_u32(sm);

    const int bx = blockIdx.x;
    const int by = blockIdx.y;
    const int w  = blockIdx.z;
    const int tid = threadIdx.x;
    const int lane = tid & 31, wid = tid >> 5;
    const int wm = wid & 3, wn = wid >> 2;
    const int hx = w >> 4, wy = w & 15;
    const bool do_mma = !(by == 2 && wm >= 2);

    float acc[2][8][4];
    #pragma unroll
    for (int mt = 0; mt < 2; mt++)
        #pragma unroll
        for (int nt = 0; nt < 8; nt++)
            #pragma unroll
            for (int r = 0; r < 4; r++) acc[mt][nt][r] = 0.f;

    const int l7 = lane & 7;
    const int g = lane >> 3;
    const uint32_t arow0 = (uint32_t)(wm * 32 + (lane & 15)) * 80;
    const int acg = lane >> 4;
    const uint32_t brow0 = (uint32_t)(wn * 64 + ((g & 2) << 2) + l7) * 80;
    const int bcg = g & 1;

    out_stage(smb, 0, 0, bx, by, w, tid);
    CP_COMMIT();

    for (int chunk = 0; chunk < 8; chunk++) {
        if (chunk < 7) {
            out_stage(smb, (chunk + 1) & 1, chunk + 1, bx, by, w, tid);
            CP_COMMIT();
            CP_WAIT1();
        } else {
            CP_WAIT0();
        }
        __syncthreads();

        if (do_mma) {
            const uint32_t sb = smb + (uint32_t)(chunk & 1) * STAGE_BYTES;
            #pragma unroll
            for (int ks = 0; ks < 2; ks++) {
                uint32_t ah[2][4], al[2][4], bh[4][4], bl[4][4];
                uint32_t akc = (uint32_t)(ks * 2 + acg) << 4;
                LDSM4(ah[0], sb + T_AHI + arow0 + akc);
                LDSM4(ah[1], sb + T_AHI + arow0 + 1280 + akc);
                LDSM4(al[0], sb + T_ALO + arow0 + akc);
                LDSM4(al[1], sb + T_ALO + arow0 + 1280 + akc);
                uint32_t bkc = (uint32_t)(ks * 2 + bcg) << 4;
                #pragma unroll
                for (int p = 0; p < 4; p++) {
                    LDSM4(bh[p], sb + T_BHI + brow0 + p * 1280 + bkc);
                    LDSM4(bl[p], sb + T_BLO + brow0 + p * 1280 + bkc);
                }
                #pragma unroll
                for (int mt = 0; mt < 2; mt++)
                    #pragma unroll
                    for (int nt = 0; nt < 8; nt++) {
                        uint32_t h0 = bh[nt >> 1][(nt & 1) * 2], h1 = bh[nt >> 1][(nt & 1) * 2 + 1];
                        uint32_t lo0 = bl[nt >> 1][(nt & 1) * 2], lo1 = bl[nt >> 1][(nt & 1) * 2 + 1];
                        MMA16816(acc[mt][nt], ah[mt], h0, h1);
                        MMA16816(acc[mt][nt], al[mt], h0, h1);
                        MMA16816(acc[mt][nt], ah[mt], lo0, lo1);
                    }
            }
        }
        __syncthreads();
    }

    const int trow = lane >> 2;
    const int tcol2 = (lane & 3) * 2;
    #pragma unroll
    for (int mt = 0; mt < 2; mt++) {
        #pragma unroll
        for (int half = 0; half < 2; half++) {
            int r = by * 128 + wm * 32 + mt * 16 + trow + half * 8;
            if (r >= NTOK) continue;
            int l = r / 49; int rem = r - l * 49; int w1 = rem / 7; int w2 = rem - w1 * 7;
            int ob = ((l * 256 + hx * 16 + wy) * 49 + w1 * 7 + w2) * 256;
            #pragma unroll
            for (int nt = 0; nt < 8; nt++) {
                int o = bx * 128 + wn * 64 + nt * 8 + tcol2;
                *(float2*)(out + ob + o) = make_float2(acc[mt][nt][half * 2],
                                                       acc[mt][nt][half * 2 + 1]);
            }
        }
    }
}

// ---------------------------------------------------------------------------
extern "C" void kernel_launch(void* const* d_in, const int* in_sizes, int n_in,
                              void* d_out, int out_size)
{
    const float* x    = (const float*)d_in[0];
    const float* wqkv = (const float*)d_in[1];
    const float* wout = (const float*)d_in[2];
    const float* bias = (const float*)d_in[3];
    float* out = (float*)d_out;

    cudaFuncSetAttribute(attn_kernel, cudaFuncAttributeMaxDynamicSharedMemorySize, ATTN_SMEM);
    cudaFuncSetAttribute(qkv_kernel, cudaFuncAttributeMaxDynamicSharedMemorySize, SM_GEMM_TOTAL);
    cudaFuncSetAttribute(out_kernel, cudaFuncAttributeMaxDynamicSharedMemorySize, SM_GEMM_TOTAL);

    split_x_kernel<<<(XSZ / 4 + 255) / 256, 256>>>(x);
    split_w_kernel<<<(768 * 256 / 4 + 256 * 256 / 4 + 255) / 256, 256>>>(wqkv, wout);
    qkv_kernel<<<dim3(6, 3, 256), 256, SM_GEMM_TOTAL>>>();
    attn_kernel<<<2048, 320, ATTN_SMEM>>>(bias);
    out_kernel<<<dim3(2, 3, 256), 256, SM_GEMM_TOTAL>>>(out);
}

// round 16
// speedup vs baseline: 1.1992x; 1.1992x over previous
#include <cuda_runtime.h>
#include <cuda_bf16.h>
#include <cstdint>

#define NTOK   294
#define NTOKP  304
#define HEADS  8
#define DH     32
#define DIM    256
#define NWIN   256
#define NBIAS  1859
#define QSCALE 0.17677669529663687f  // 32^-0.5
#define LOG2E  1.4426950408889634f
#define XSZ    (6 * 16 * 16 * 7 * 7 * 256)   // 19267584

// ---------------- scratch (allocation-free: __device__ globals) -------------
__device__ __nv_bfloat16 g_x_hi[XSZ];
__device__ __nv_bfloat16 g_x_lo[XSZ];
__device__ __nv_bfloat16 g_wq_hi[768 * 256];
__device__ __nv_bfloat16 g_wq_lo[768 * 256];
__device__ __nv_bfloat16 g_wo_hi[256 * 256];
__device__ __nv_bfloat16 g_wo_lo[256 * 256];
// q/k/v as bf16 hi/lo, layout [wh][NTOK][32]
__device__ __nv_bfloat16 g_qh[NWIN * HEADS * NTOK * DH];
__device__ __nv_bfloat16 g_ql[NWIN * HEADS * NTOK * DH];
__device__ __nv_bfloat16 g_kh[NWIN * HEADS * NTOK * DH];
__device__ __nv_bfloat16 g_kl[NWIN * HEADS * NTOK * DH];
__device__ __nv_bfloat16 g_vh[NWIN * HEADS * NTOK * DH];
__device__ __nv_bfloat16 g_vl[NWIN * HEADS * NTOK * DH];
// attention output as bf16 hi/lo, layout [w][tok][256]
__device__ __nv_bfloat16 g_oh[NWIN * NTOK * DIM];
__device__ __nv_bfloat16 g_ol[NWIN * NTOK * DIM];

// ---------------- helpers ---------------------------------------------------
__device__ __forceinline__ uint32_t smem_u32(const void* p) {
    uint32_t a;
    asm("{ .reg .u64 t; cvta.to.shared.u64 t, %1; cvt.u32.u64 %0, t; }" : "=r"(a) : "l"(p));
    return a;
}

#define LDSM4(r, a) \
    asm volatile("ldmatrix.sync.aligned.m8n8.x4.shared.b16 {%0,%1,%2,%3}, [%4];" \
        : "=r"((r)[0]), "=r"((r)[1]), "=r"((r)[2]), "=r"((r)[3]) : "r"(a))
#define LDSM4T(r, a) \
    asm volatile("ldmatrix.sync.aligned.m8n8.x4.trans.shared.b16 {%0,%1,%2,%3}, [%4];" \
        : "=r"((r)[0]), "=r"((r)[1]), "=r"((r)[2]), "=r"((r)[3]) : "r"(a))

#define MMA16816(d, a, b0, b1) \
    asm volatile("mma.sync.aligned.m16n8k16.row.col.f32.bf16.bf16.f32 " \
        "{%0,%1,%2,%3}, {%4,%5,%6,%7}, {%8,%9}, {%0,%1,%2,%3};" \
        : "+f"((d)[0]), "+f"((d)[1]), "+f"((d)[2]), "+f"((d)[3]) \
        : "r"((a)[0]), "r"((a)[1]), "r"((a)[2]), "r"((a)[3]), "r"(b0), "r"(b1))

#define CP16(dst, src, sz) \
    asm volatile("cp.async.cg.shared.global [%0], [%1], 16, %2;" \
        :: "r"(dst), "l"(src), "r"(sz))
#define CP_COMMIT() asm volatile("cp.async.commit_group;" ::: "memory")
#define CP_WAIT1()  asm volatile("cp.async.wait_group 1;" ::: "memory")
#define CP_WAIT0()  asm volatile("cp.async.wait_group 0;" ::: "memory")

#define EX2F(d, x) asm("ex2.approx.f32 %0, %1;" : "=f"(d) : "f"(x))

// pack two floats into bf16x2 (one cvt instruction)
__device__ __forceinline__ uint32_t pack2(float lo, float hi) {
    uint32_t r;
    asm("cvt.rn.bf16x2.f32 %0, %1, %2;" : "=r"(r) : "f"(hi), "f"(lo));
    return r;
}
// hi/lo split pair
__device__ __forceinline__ void pack_hl(float a, float b, uint32_t& hi, uint32_t& lo) {
    hi = pack2(a, b);
    float fa = __uint_as_float(hi << 16);
    float fb = __uint_as_float(hi & 0xffff0000u);
    lo = pack2(a - fa, b - fb);
}
__device__ __forceinline__ void split_pack(float4 v, uint2& hi, uint2& lo) {
    pack_hl(v.x, v.y, hi.x, lo.x);
    pack_hl(v.z, v.w, hi.y, lo.y);
}

// GEMM smem: 2 stages x (AHI|ALO|BHI|BLO); tile = 128 rows x 32 cols bf16,
// 80B padded row stride -> conflict-free, no swizzle.
#define TILE_BYTES 10240
#define STAGE_BYTES 40960
#define T_AHI 0
#define T_ALO 10240
#define T_BHI 20480
#define T_BLO 30720
#define SM_RB (2 * STAGE_BYTES)
#define SM_GEMM_TOTAL (2 * STAGE_BYTES + 512)

// attention smem layout (bytes); rows padded to 40 bf16 = 80B
#define A_KH 0
#define A_KL 24320
#define A_VH 48640
#define A_VL 72960
#define A_BH 97280                      // 1859 floats (pre-scaled by log2e)
#define A_CJ 104716                     // 304 ints
#define ATTN_SMEM 105936

// ---------------- merged prep kernel ----------------------------------------
#define NX4 (XSZ / 4)
#define NQ4 (768 * 256 / 4)
#define NO4 (256 * 256 / 4)
__global__ __launch_bounds__(256) void split_kernel(const float* __restrict__ x,
                                                    const float* __restrict__ wqkv,
                                                    const float* __restrict__ wout)
{
    int i = blockIdx.x * blockDim.x + threadIdx.x;
    if (i < NX4) {
        float4 v = ((const float4*)x)[i];
        uint2 hi, lo;
        split_pack(v, hi, lo);
        ((uint2*)g_x_hi)[i] = hi;
        ((uint2*)g_x_lo)[i] = lo;
    } else if (i < NX4 + NQ4) {
        int j = i - NX4;
        float4 v = ((const float4*)wqkv)[j];
        uint2 hi, lo;
        split_pack(v, hi, lo);
        ((uint2*)g_wq_hi)[j] = hi;
        ((uint2*)g_wq_lo)[j] = lo;
    } else if (i < NX4 + NQ4 + NO4) {
        int j = i - NX4 - NQ4;
        float4 v = ((const float4*)wout)[j];
        uint2 hi, lo;
        split_pack(v, hi, lo);
        ((uint2*)g_wo_hi)[j] = hi;
        ((uint2*)g_wo_lo)[j] = lo;
    }
}

// ---------------- stage loaders (cp.async, 16B granules, 32-col chunks) -----
__device__ __forceinline__ void qkv_stage(uint32_t smb, int stg, int chunk,
                                          const int* rb, int bx, int tid)
{
    #pragma unroll
    for (int i = 0; i < 8; i++) {
        int u = tid + i * 256;
        int tile = u >> 9;
        int uu = u & 511;
        int row = uu >> 2, kc = uu & 3;
        uint32_t dst = smb + (uint32_t)stg * STAGE_BYTES + tile * TILE_BYTES
                       + row * 80 + kc * 16;
        const __nv_bfloat16* src;
        uint32_t sz = 16;
        if (tile < 2) {
            int base = rb[row];
            if (base < 0) { sz = 0; base = 0; }
            src = (tile == 0 ? g_x_hi : g_x_lo) + base + chunk * 32 + kc * 8;
        } else {
            int nrow = bx * 128 + row;
            src = (tile == 2 ? g_wq_hi : g_wq_lo) + nrow * 256 + chunk * 32 + kc * 8;
        }
        CP16(dst, src, sz);
    }
}

__device__ __forceinline__ void out_stage(uint32_t smb, int stg, int chunk,
                                          int bx, int by, int w, int tid)
{
    #pragma unroll
    for (int i = 0; i < 8; i++) {
        int u = tid + i * 256;
        int tile = u >> 9;
        int uu = u & 511;
        int row = uu >> 2, kc = uu & 3;
        uint32_t dst = smb + (uint32_t)stg * STAGE_BYTES + tile * TILE_BYTES
                       + row * 80 + kc * 16;
        const __nv_bfloat16* src;
        uint32_t sz = 16;
        if (tile < 2) {
            int tok = by * 128 + row;
            size_t base = 0;
            if (tok < NTOK) base = ((size_t)w * NTOK + tok) * DIM;
            else sz = 0;
            src = (tile == 0 ? g_oh : g_ol) + base + chunk * 32 + kc * 8;
        } else {
            int nrow = bx * 128 + row;
            src = (tile == 2 ? g_wo_hi : g_wo_lo) + nrow * 256 + chunk * 32 + kc * 8;
        }
        CP16(dst, src, sz);
    }
}

// ---------------------------------------------------------------------------
// Kernel 1: QKV GEMM, cp.async 2-stage pipeline (32-col chunks, 80B rows),
// mma.sync bf16 3-pass. grid (6, 3, 256), block 256, 2 CTAs/SM.
// ---------------------------------------------------------------------------
__global__ __launch_bounds__(256, 2) void qkv_kernel()
{
    extern __shared__ char sm[];
    const uint32_t smb = smem_u32(sm);
    int* rb = (int*)(sm + SM_RB);

    const int bx = blockIdx.x;
    const int by = blockIdx.y;
    const int w  = blockIdx.z;
    const int tid = threadIdx.x;
    const int lane = tid & 31, wid = tid >> 5;
    const int wm = wid & 3, wn = wid >> 2;
    const int hx = w >> 4, wy = w & 15;

    if (tid < 128) {
        int n = by * 128 + tid;
        if (n < NTOK) {
            int l = n / 49; int rem = n - l * 49; int w1 = rem / 7; int w2 = rem - w1 * 7;
            rb[tid] = ((l * 256 + hx * 16 + wy) * 49 + w1 * 7 + w2) * 256;
        } else rb[tid] = -1;
    }
    __syncthreads();

    float acc[2][8][4];
    #pragma unroll
    for (int mt = 0; mt < 2; mt++)
        #pragma unroll
        for (int nt = 0; nt < 8; nt++)
            #pragma unroll
            for (int r = 0; r < 4; r++) acc[mt][nt][r] = 0.f;

    const int l7 = lane & 7;
    const int g = lane >> 3;
    const uint32_t arow0 = (uint32_t)(wm * 32 + (lane & 15)) * 80;
    const int acg = lane >> 4;
    const uint32_t brow0 = (uint32_t)(wn * 64 + ((g & 2) << 2) + l7) * 80;
    const int bcg = g & 1;

    qkv_stage(smb, 0, 0, rb, bx, tid);
    CP_COMMIT();

    for (int chunk = 0; chunk < 8; chunk++) {
        if (chunk < 7) {
            qkv_stage(smb, (chunk + 1) & 1, chunk + 1, rb, bx, tid);
            CP_COMMIT();
            CP_WAIT1();
        } else {
            CP_WAIT0();
        }
        __syncthreads();

        const uint32_t sb = smb + (uint32_t)(chunk & 1) * STAGE_BYTES;
        #pragma unroll
        for (int ks = 0; ks < 2; ks++) {
            uint32_t ah[2][4], al[2][4], bh[4][4], bl[4][4];
            uint32_t akc = (uint32_t)(ks * 2 + acg) << 4;
            LDSM4(ah[0], sb + T_AHI + arow0 + akc);
            LDSM4(ah[1], sb + T_AHI + arow0 + 1280 + akc);
            LDSM4(al[0], sb + T_ALO + arow0 + akc);
            LDSM4(al[1], sb + T_ALO + arow0 + 1280 + akc);
            uint32_t bkc = (uint32_t)(ks * 2 + bcg) << 4;
            #pragma unroll
            for (int p = 0; p < 4; p++) {
                LDSM4(bh[p], sb + T_BHI + brow0 + p * 1280 + bkc);
                LDSM4(bl[p], sb + T_BLO + brow0 + p * 1280 + bkc);
            }
            #pragma unroll
            for (int mt = 0; mt < 2; mt++)
                #pragma unroll
                for (int nt = 0; nt < 8; nt++) {
                    uint32_t h0 = bh[nt >> 1][(nt & 1) * 2], h1 = bh[nt >> 1][(nt & 1) * 2 + 1];
                    uint32_t lo0 = bl[nt >> 1][(nt & 1) * 2], lo1 = bl[nt >> 1][(nt & 1) * 2 + 1];
                    MMA16816(acc[mt][nt], ah[mt], h0, h1);
                    MMA16816(acc[mt][nt], al[mt], h0, h1);
                    MMA16816(acc[mt][nt], ah[mt], lo0, lo1);
                }
        }
        __syncthreads();
    }

    // ---- epilogue: split + scatter to bf16 hi/lo q/k/v ---------------------
    const int part = bx >> 1;
    __nv_bfloat16* dh_ = (part == 0) ? g_qh : (part == 1) ? g_kh : g_vh;
    __nv_bfloat16* dl_ = (part == 0) ? g_ql : (part == 1) ? g_kl : g_vl;
    const float scale = (part == 0) ? QSCALE : 1.f;
    const int trow = lane >> 2;
    const int tcol2 = (lane & 3) * 2;

    #pragma unroll
    for (int mt = 0; mt < 2; mt++) {
        #pragma unroll
        for (int half = 0; half < 2; half++) {
            int r = by * 128 + wm * 32 + mt * 16 + trow + half * 8;
            if (r >= NTOK) continue;
            #pragma unroll
            for (int nt = 0; nt < 8; nt++) {
                int o = bx * 128 + wn * 64 + nt * 8 + tcol2;
                int hh = (o & 255) >> 5, d = o & 31;
                uint32_t hip, lop;
                pack_hl(acc[mt][nt][half * 2] * scale,
                        acc[mt][nt][half * 2 + 1] * scale, hip, lop);
                size_t off = ((size_t)(w * 8 + hh) * NTOK + r) * 32 + d;
                *(uint32_t*)(dh_ + off) = hip;
                *(uint32_t*)(dl_ + off) = lop;
            }
        }
    }
}

// ---------------------------------------------------------------------------
// Kernel 2: tensor-core attention. One CTA per (window, head), 320 threads.
// Mask folded into prefetched bias (-60 for pad cols) -> branch/sel-free
// hot path: p = ex2(fma(S, log2e, bbm)).
// ---------------------------------------------------------------------------
__global__ __launch_bounds__(320, 2) void attn_kernel(const float* __restrict__ bias_table)
{
    extern __shared__ char sm[];
    const uint32_t smb = smem_u32(sm);
    float* bH  = (float*)(sm + A_BH);
    int*   cjs = (int*)(sm + A_CJ);

    const int wh = blockIdx.x;
    const int h  = wh & 7;
    const int w  = wh >> 3;
    const int tid = threadIdx.x;
    const int lane = tid & 31, wm = tid >> 5;
    const int t4 = lane & 3, g = lane >> 2;
    const size_t base = (size_t)wh * NTOK * DH;

    {
        const __nv_bfloat16* srcs[4] = {g_kh + base, g_kl + base, g_vh + base, g_vl + base};
        const uint32_t dsts[4] = {A_KH, A_KL, A_VH, A_VL};
        for (int idx = tid; idx < 4 * NTOKP * 4; idx += 320) {
            int arr = idx / (NTOKP * 4);
            int rem = idx - arr * (NTOKP * 4);
            int row = rem >> 2, seg = rem & 3;
            uint32_t sz = (row < NTOK) ? 16u : 0u;
            int srow = (row < NTOK) ? row : 0;
            CP16(smb + dsts[arr] + row * 80 + seg * 16, srcs[arr] + srow * 32 + seg * 8, sz);
        }
        CP_COMMIT();
        for (int i = tid; i < NBIAS; i += 320) bH[i] = bias_table[i * HEADS + h] * LOG2E;
        for (int i = tid; i < NTOKP; i += 320) {
            if (i < NTOK) {
                int l = i / 49, rem = i - l * 49, w1 = rem / 7, w2 = rem - w1 * 7;
                cjs[i] = l * 169 + w1 * 13 + w2;
            } else cjs[i] = 0;
        }
    }

    const int R = wm * 32;
    uint32_t aQh[2][2][4], aQl[2][2][4];
    #pragma unroll
    for (int mt = 0; mt < 2; mt++) {
        int r0 = R + mt * 16 + g, r1 = r0 + 8;
        #pragma unroll
        for (int kh = 0; kh < 2; kh++) {
            int c0 = kh * 16 + 2 * t4, c1 = c0 + 8;
            aQh[mt][kh][0] = (r0 < NTOK) ? *(const uint32_t*)(g_qh + base + r0 * 32 + c0) : 0u;
            aQh[mt][kh][1] = (r1 < NTOK) ? *(const uint32_t*)(g_qh + base + r1 * 32 + c0) : 0u;
            aQh[mt][kh][2] = (r0 < NTOK) ? *(const uint32_t*)(g_qh + base + r0 * 32 + c1) : 0u;
            aQh[mt][kh][3] = (r1 < NTOK) ? *(const uint32_t*)(g_qh + base + r1 * 32 + c1) : 0u;
            aQl[mt][kh][0] = (r0 < NTOK) ? *(const uint32_t*)(g_ql + base + r0 * 32 + c0) : 0u;
            aQl[mt][kh][1] = (r1 < NTOK) ? *(const uint32_t*)(g_ql + base + r1 * 32 + c0) : 0u;
            aQl[mt][kh][2] = (r0 < NTOK) ? *(const uint32_t*)(g_ql + base + r0 * 32 + c1) : 0u;
            aQl[mt][kh][3] = (r1 < NTOK) ? *(const uint32_t*)(g_ql + base + r1 * 32 + c1) : 0u;
        }
    }
    CP_WAIT0();
    __syncthreads();

    int ci[2][2];
    #pragma unroll
    for (int mt = 0; mt < 2; mt++) {
        int r0 = R + mt * 16 + g, r1 = r0 + 8;
        ci[mt][0] = cjs[r0 < NTOK ? r0 : NTOK - 1] + 929;
        ci[mt][1] = cjs[r1 < NTOK ? r1 : NTOK - 1] + 929;
    }

    float O[2][4][4];
    #pragma unroll
    for (int mt = 0; mt < 2; mt++)
        #pragma unroll
        for (int dn = 0; dn < 4; dn++)
            #pragma unroll
            for (int e = 0; e < 4; e++) O[mt][dn][e] = 0.f;
    float rs[2][2] = {{0.f, 0.f}, {0.f, 0.f}};

    const int lrow = ((lane & 8) ? 8 : 0) + (lane & 7);
    const int lcol = (lane & 16) ? 8 : 0;

    for (int j0 = 0; j0 < NTOKP; j0 += 16) {
        // ---- bias+mask prefetch (independent of S) ------------------------
        float bbm[2][2][4];
        {
            int   cjv[2][2];
            bool  va[2][2];
            #pragma unroll
            for (int jn = 0; jn < 2; jn++) {
                int jb = j0 + 8 * jn + 2 * t4;
                cjv[jn][0] = cjs[jb];
                cjv[jn][1] = cjs[jb + 1];
                va[jn][0] = (jb < NTOK);
                va[jn][1] = (jb + 1 < NTOK);
            }
            #pragma unroll
            for (int mt = 0; mt < 2; mt++)
                #pragma unroll
                for (int jn = 0; jn < 2; jn++) {
                    bbm[mt][jn][0] = va[jn][0] ? bH[ci[mt][0] - cjv[jn][0]] : -60.f;
                    bbm[mt][jn][1] = va[jn][1] ? bH[ci[mt][0] - cjv[jn][1]] : -60.f;
                    bbm[mt][jn][2] = va[jn][0] ? bH[ci[mt][1] - cjv[jn][0]] : -60.f;
                    bbm[mt][jn][3] = va[jn][1] ? bH[ci[mt][1] - cjv[jn][1]] : -60.f;
                }
        }

        // ---- K + V fragments ---------------------------------------------
        uint32_t bkh[2][2][2], bkl[2][2][2];
        #pragma unroll
        for (int kh = 0; kh < 2; kh++) {
            uint32_t addr = (uint32_t)((j0 + lrow) * 80 + (kh * 16 + lcol) * 2);
            uint32_t t[4];
            LDSM4(t, smb + A_KH + addr);
            bkh[0][kh][0] = t[0]; bkh[0][kh][1] = t[2];
            bkh[1][kh][0] = t[1]; bkh[1][kh][1] = t[3];
            LDSM4(t, smb + A_KL + addr);
            bkl[0][kh][0] = t[0]; bkl[0][kh][1] = t[2];
            bkl[1][kh][0] = t[1]; bkl[1][kh][1] = t[3];
        }
        uint32_t bvh[4][2], bvl[4][2];
        #pragma unroll
        for (int dh2 = 0; dh2 < 2; dh2++) {
            uint32_t addr = (uint32_t)((j0 + lrow) * 80 + (dh2 * 16 + lcol) * 2);
            uint32_t t[4];
            LDSM4T(t, smb + A_VH + addr);
            bvh[dh2 * 2][0] = t[0]; bvh[dh2 * 2][1] = t[1];
            bvh[dh2 * 2 + 1][0] = t[2]; bvh[dh2 * 2 + 1][1] = t[3];
            LDSM4T(t, smb + A_VL + addr);
            bvl[dh2 * 2][0] = t[0]; bvl[dh2 * 2][1] = t[1];
            bvl[dh2 * 2 + 1][0] = t[2]; bvl[dh2 * 2 + 1][1] = t[3];
        }

        // ---- S = Q K^T (3-pass hi/lo) ------------------------------------
        float S[2][2][4];
        #pragma unroll
        for (int mt = 0; mt < 2; mt++)
            #pragma unroll
            for (int jn = 0; jn < 2; jn++) {
                #pragma unroll
                for (int e = 0; e < 4; e++) S[mt][jn][e] = 0.f;
                #pragma unroll
                for (int kh = 0; kh < 2; kh++) {
                    MMA16816(S[mt][jn], aQh[mt][kh], bkh[jn][kh][0], bkh[jn][kh][1]);
                    MMA16816(S[mt][jn], aQl[mt][kh], bkh[jn][kh][0], bkh[jn][kh][1]);
                    MMA16816(S[mt][jn], aQh[mt][kh], bkl[jn][kh][0], bkl[jn][kh][1]);
                }
            }

        // ---- p = 2^(S*log2e + bbm); sel-free hot path --------------------
        uint32_t aPh[2][4], aPl[2][4];
        #pragma unroll
        for (int mt = 0; mt < 2; mt++) {
            float p[2][4];
            #pragma unroll
            for (int jn = 0; jn < 2; jn++) {
                #pragma unroll
                for (int e = 0; e < 4; e++) {
                    float arg = fmaf(S[mt][jn][e], LOG2E, bbm[mt][jn][e]);
                    EX2F(p[jn][e], arg);
                }
                rs[mt][0] += p[jn][0] + p[jn][1];
                rs[mt][1] += p[jn][2] + p[jn][3];
            }
            pack_hl(p[0][0], p[0][1], aPh[mt][0], aPl[mt][0]);
            pack_hl(p[0][2], p[0][3], aPh[mt][1], aPl[mt][1]);
            pack_hl(p[1][0], p[1][1], aPh[mt][2], aPl[mt][2]);
            pack_hl(p[1][2], p[1][3], aPh[mt][3], aPl[mt][3]);
        }

        // ---- O += P V (3-pass hi/lo) -------------------------------------
        #pragma unroll
        for (int mt = 0; mt < 2; mt++)
            #pragma unroll
            for (int dn = 0; dn < 4; dn++) {
                MMA16816(O[mt][dn], aPh[mt], bvh[dn][0], bvh[dn][1]);
                MMA16816(O[mt][dn], aPl[mt], bvh[dn][0], bvh[dn][1]);
                MMA16816(O[mt][dn], aPh[mt], bvl[dn][0], bvl[dn][1]);
            }
    }

    // ---- normalize + write bf16 hi/lo O -----------------------------------
    #pragma unroll
    for (int mt = 0; mt < 2; mt++)
        #pragma unroll
        for (int h2 = 0; h2 < 2; h2++) {
            float v = rs[mt][h2];
            v += __shfl_xor_sync(0xFFFFFFFFu, v, 1);
            v += __shfl_xor_sync(0xFFFFFFFFu, v, 2);
            rs[mt][h2] = 1.f / v;
        }
    #pragma unroll
    for (int mt = 0; mt < 2; mt++)
        #pragma unroll
        for (int h2 = 0; h2 < 2; h2++) {
            int row = R + mt * 16 + g + 8 * h2;
            if (row >= NTOK) continue;
            float inv = rs[mt][h2];
            size_t ob = ((size_t)w * NTOK + row) * DIM + h * DH;
            #pragma unroll
            for (int dn = 0; dn < 4; dn++) {
                int col = dn * 8 + 2 * t4;
                uint32_t hip, lop;
                pack_hl(O[mt][dn][h2 * 2] * inv, O[mt][dn][h2 * 2 + 1] * inv, hip, lop);
                *(uint32_t*)(g_oh + ob + col) = hip;
                *(uint32_t*)(g_ol + ob + col) = lop;
            }
        }
}

// ---------------------------------------------------------------------------
// Kernel 3: output GEMM, cp.async 2-stage pipeline (32-col chunks, 80B rows),
// mma.sync bf16 3-pass. grid (2, 3, 256), block 256, 2 CTAs/SM.
// ---------------------------------------------------------------------------
__global__ __launch_bounds__(256, 2) void out_kernel(float* __restrict__ out)
{
    extern __shared__ char sm[];
    const uint32_t smb = smem_u32(sm);

    const int bx = blockIdx.x;
    const int by = blockIdx.y;
    const int w  = blockIdx.z;
    const int tid = threadIdx.x;
    const int lane = tid & 31, wid = tid >> 5;
    const int wm = wid & 3, wn = wid >> 2;
    const int hx = w >> 4, wy = w & 15;

    float acc[2][8][4];
    #pragma unroll
    for (int mt = 0; mt < 2; mt++)
        #pragma unroll
        for (int nt = 0; nt < 8; nt++)
            #pragma unroll
            for (int r = 0; r < 4; r++) acc[mt][nt][r] = 0.f;

    const int l7 = lane & 7;
    const int g = lane >> 3;
    const uint32_t arow0 = (uint32_t)(wm * 32 + (lane & 15)) * 80;
    const int acg = lane >> 4;
    const uint32_t brow0 = (uint32_t)(wn * 64 + ((g & 2) << 2) + l7) * 80;
    const int bcg = g & 1;

    out_stage(smb, 0, 0, bx, by, w, tid);
    CP_COMMIT();

    for (int chunk = 0; chunk < 8; chunk++) {
        if (chunk < 7) {
            out_stage(smb, (chunk + 1) & 1, chunk + 1, bx, by, w, tid);
            CP_COMMIT();
            CP_WAIT1();
        } else {
            CP_WAIT0();
        }
        __syncthreads();

        const uint32_t sb = smb + (uint32_t)(chunk & 1) * STAGE_BYTES;
        #pragma unroll
        for (int ks = 0; ks < 2; ks++) {
            uint32_t ah[2][4], al[2][4], bh[4][4], bl[4][4];
            uint32_t akc = (uint32_t)(ks * 2 + acg) << 4;
            LDSM4(ah[0], sb + T_AHI + arow0 + akc);
            LDSM4(ah[1], sb + T_AHI + arow0 + 1280 + akc);
            LDSM4(al[0], sb + T_ALO + arow0 + akc);
            LDSM4(al[1], sb + T_ALO + arow0 + 1280 + akc);
            uint32_t bkc = (uint32_t)(ks * 2 + bcg) << 4;
            #pragma unroll
            for (int p = 0; p < 4; p++) {
                LDSM4(bh[p], sb + T_BHI + brow0 + p * 1280 + bkc);
                LDSM4(bl[p], sb + T_BLO + brow0 + p * 1280 + bkc);
            }
            #pragma unroll
            for (int mt = 0; mt < 2; mt++)
                #pragma unroll
                for (int nt = 0; nt < 8; nt++) {
                    uint32_t h0 = bh[nt >> 1][(nt & 1) * 2], h1 = bh[nt >> 1][(nt & 1) * 2 + 1];
                    uint32_t lo0 = bl[nt >> 1][(nt & 1) * 2], lo1 = bl[nt >> 1][(nt & 1) * 2 + 1];
                    MMA16816(acc[mt][nt], ah[mt], h0, h1);
                    MMA16816(acc[mt][nt], al[mt], h0, h1);
                    MMA16816(acc[mt][nt], ah[mt], lo0, lo1);
                }
        }
        __syncthreads();
    }

    const int trow = lane >> 2;
    const int tcol2 = (lane & 3) * 2;
    #pragma unroll
    for (int mt = 0; mt < 2; mt++) {
        #pragma unroll
        for (int half = 0; half < 2; half++) {
            int r = by * 128 + wm * 32 + mt * 16 + trow + half * 8;
            if (r >= NTOK) continue;
            int l = r / 49; int rem = r - l * 49; int w1 = rem / 7; int w2 = rem - w1 * 7;
            int ob = ((l * 256 + hx * 16 + wy) * 49 + w1 * 7 + w2) * 256;
            #pragma unroll
            for (int nt = 0; nt < 8; nt++) {
                int o = bx * 128 + wn * 64 + nt * 8 + tcol2;
                *(float2*)(out + ob + o) = make_float2(acc[mt][nt][half * 2],
                                                       acc[mt][nt][half * 2 + 1]);
            }
        }
    }
}

// ---------------------------------------------------------------------------
extern "C" void kernel_launch(void* const* d_in, const int* in_sizes, int n_in,
                              void* d_out, int out_size)
{
    const float* x    = (const float*)d_in[0];
    const float* wqkv = (const float*)d_in[1];
    const float* wout = (const float*)d_in[2];
    const float* bias = (const float*)d_in[3];
    float* out = (float*)d_out;

    cudaFuncSetAttribute(attn_kernel, cudaFuncAttributeMaxDynamicSharedMemorySize, ATTN_SMEM);
    cudaFuncSetAttribute(qkv_kernel, cudaFuncAttributeMaxDynamicSharedMemorySize, SM_GEMM_TOTAL);
    cudaFuncSetAttribute(out_kernel, cudaFuncAttributeMaxDynamicSharedMemorySize, SM_GEMM_TOTAL);

    split_kernel<<<(NX4 + NQ4 + NO4 + 255) / 256, 256>>>(x, wqkv, wout);
    qkv_kernel<<<dim3(6, 3, 256), 256, SM_GEMM_TOTAL>>>();
    attn_kernel<<<2048, 320, ATTN_SMEM>>>(bias);
    out_kernel<<<dim3(2, 3, 256), 256, SM_GEMM_TOTAL>>>(out);
}